// round 14
// baseline (speedup 1.0000x reference)
#include <cuda_runtime.h>

// Problem constants (fixed by the dataset)
#define MAXN 50000
#define MAXE 800000

typedef unsigned long long u64;

// Persistent device scratch (allocation-free rule: __device__ globals)
static __device__ __align__(16) float g_sup[MAXN * 32];     // s_up   [n][c]
static __device__ __align__(16) float g_vup[MAXN * 96];     // v_up   [n][x][c]
static __device__ __align__(16) float g_skip_s[MAXN * 64];  // skip_s [n][d]
static __device__ __align__(16) float g_skip_v[MAXN * 96];  // skip_v [n][x][c]
static __device__ __align__(16) float g_agg[MAXN * 256];    // [n][slot][c]

__device__ __forceinline__ float silu_f(float x) {
    return x / (1.0f + __expf(-x));
}

__device__ __forceinline__ void red_add_v4(float* p, float a, float b, float c, float d) {
    asm volatile("red.global.add.v4.f32 [%0], {%1,%2,%3,%4};"
                 :: "l"(p), "f"(a), "f"(b), "f"(c), "f"(d)
                 : "memory");
}

// ---- packed f32x2 helpers (Blackwell FFMA2 path) ----
__device__ __forceinline__ u64 pack2(float lo, float hi) {
    u64 r; asm("mov.b64 %0, {%1, %2};" : "=l"(r) : "f"(lo), "f"(hi)); return r;
}
__device__ __forceinline__ void unpack2(u64 p, float& lo, float& hi) {
    asm("mov.b64 {%0, %1}, %2;" : "=f"(lo), "=f"(hi) : "l"(p));
}
__device__ __forceinline__ u64 fma2(u64 a, u64 b, u64 c) {
    u64 d; asm("fma.rn.f32x2 %0, %1, %2, %3;" : "=l"(d) : "l"(a), "l"(b), "l"(c)); return d;
}
__device__ __forceinline__ u64 mul2(u64 a, u64 b) {
    u64 d; asm("mul.rn.f32x2 %0, %1, %2;" : "=l"(d) : "l"(a), "l"(b)); return d;
}

// ---------------------------------------------------------------------------
// Kernel A: per-node up-projection + species skip (round-1 champion version,
// 1 node per warp; also zeroes this node's agg slab).
// ---------------------------------------------------------------------------
__global__ void node_up_kernel(const float* __restrict__ nf,
                               const int*   __restrict__ species,
                               const float* __restrict__ Wus,   // (32,32)
                               const float* __restrict__ Wuv,   // (32,32)
                               const float* __restrict__ Wss,   // (5,32,64)
                               const float* __restrict__ Wsv,   // (5,32,32)
                               int N)
{
    int warp = (blockIdx.x * blockDim.x + threadIdx.x) >> 5;
    int lane = threadIdx.x & 31;
    if (warp >= N) return;
    int n = warp;

    const float* nfp = nf + (size_t)n * 128;
    float s  = nfp[lane];
    float v0 = nfp[32 + lane * 3 + 0];
    float v1 = nfp[32 + lane * 3 + 1];
    float v2 = nfp[32 + lane * 3 + 2];
    int sp = species[n];
    const float* wss = Wss + sp * 2048;
    const float* wsv = Wsv + sp * 1024;

    float sup = 0.f, vu0 = 0.f, vu1 = 0.f, vu2 = 0.f;
    float ss0 = 0.f, ss1 = 0.f, sv0 = 0.f, sv1 = 0.f, sv2 = 0.f;

    #pragma unroll
    for (int c = 0; c < 32; ++c) {
        float sb = __shfl_sync(0xffffffffu, s,  c);
        float b0 = __shfl_sync(0xffffffffu, v0, c);
        float b1 = __shfl_sync(0xffffffffu, v1, c);
        float b2 = __shfl_sync(0xffffffffu, v2, c);
        sup = fmaf(sb, __ldg(Wus + c * 32 + lane), sup);
        float wu = __ldg(Wuv + c * 32 + lane);
        vu0 = fmaf(b0, wu, vu0);
        vu1 = fmaf(b1, wu, vu1);
        vu2 = fmaf(b2, wu, vu2);
        ss0 = fmaf(sb, __ldg(wss + c * 64 + lane), ss0);
        ss1 = fmaf(sb, __ldg(wss + c * 64 + 32 + lane), ss1);
        float wv = __ldg(wsv + c * 32 + lane);
        sv0 = fmaf(b0, wv, sv0);
        sv1 = fmaf(b1, wv, sv1);
        sv2 = fmaf(b2, wv, sv2);
    }

    const float isc = 0.17677669529663687f; // 1/sqrt(32)
    g_sup[n * 32 + lane]             = sup * isc;
    g_vup[n * 96 + 0 * 32 + lane]    = vu0 * isc;
    g_vup[n * 96 + 1 * 32 + lane]    = vu1 * isc;
    g_vup[n * 96 + 2 * 32 + lane]    = vu2 * isc;
    g_skip_s[n * 64 + lane]          = ss0 * isc;
    g_skip_s[n * 64 + 32 + lane]     = ss1 * isc;
    g_skip_v[n * 96 + 0 * 32 + lane] = sv0 * isc;
    g_skip_v[n * 96 + 1 * 32 + lane] = sv1 * isc;
    g_skip_v[n * 96 + 2 * 32 + lane] = sv2 * isc;

    #pragma unroll
    for (int k = 0; k < 2; ++k)
        *(float4*)(g_agg + n * 256 + (k * 32 + lane) * 4) = make_float4(0.f, 0.f, 0.f, 0.f);
}

// ---------------------------------------------------------------------------
// Kernel B: edge kernel, 8 edges per warp, branch-free body.
// Round-14 change: h + snd/rcv staged in smem once per warp; per-edge reads
// via uniform LDS.128/LDS.64 broadcasts (replaces 8 h-shfl + 2 idx-shfl per
// edge with 2 LDS.128 + 1 LDS.64 -> ~30% fewer MIO ops/edge).
// ---------------------------------------------------------------------------
__global__ void __launch_bounds__(256, 3) edge_kernel(
    const float* __restrict__ ef,
    const float* __restrict__ radial,
    const int*   __restrict__ snd_,
    const int*   __restrict__ rcv_,
    const float* __restrict__ Wr1,   // (8,8)
    const float* __restrict__ Wr2,   // (8,128)
    int E)
{
    __shared__ __align__(16) float sm_h[8][64];   // [warp][edge*8+hid]
    __shared__ __align__(8)  int   sm_ix[8][16];  // [warp][edge*2 + {snd,rcv}]

    int warp = (blockIdx.x * blockDim.x + threadIdx.x) >> 5;
    int lane = threadIdx.x & 31;
    int wib  = (threadIdx.x >> 5) & 7;
    int base = warp * 8;
    if (base >= E) return;

    const float inv_sqrt8 = 0.35355339059327373f;
    const float inv_sqrt3 = 0.5773502691896258f;
    const float wk        = 0.08838834764831845f; // inv_sqrt8 * 1/sqrt(16)

    int grp  = lane >> 3;
    int pA   = (grp == 0) ? 0 : ((grp == 1) ? 3 : ((grp == 2) ? 1 : 2));
    int srcB = (grp < 2) ? lane + 16 : lane;
    int cidx = (lane & 7) * 4;
    int jj   = lane & 7;
    int loff = (lane >> 4) * 64 + (lane & 15) * 4;

    bool g1 = (grp == 1), g2 = (grp == 2), g3 = (grp == 3);
    bool g0 = (grp == 0);
    bool scalA = ((grp & 1) == 0);

    int wcol = pA * 32 + cidx;
    u64 wr2p0[8], wr2p1[8];
    #pragma unroll
    for (int q = 0; q < 8; ++q) {
        float4 wr = __ldg((const float4*)(Wr2 + q * 128 + wcol));
        wr2p0[q] = pack2(wr.x, wr.y);
        wr2p1[q] = pack2(wr.z, wr.w);
    }
    u64 wk2   = pack2(wk, wk);
    u64 zero2 = pack2(0.f, 0.f);

    // ---- batch phase: h for all 8 edges + indices, staged to smem ----
    {
        float wr1r[8];
        #pragma unroll
        for (int i = 0; i < 8; ++i) wr1r[i] = __ldg(Wr1 + i * 8 + jj);

        int eic = base + jj; if (eic > E - 1) eic = E - 1;
        int snd8 = __ldg(snd_ + eic);
        int rcv8 = __ldg(rcv_ + eic);

        size_t rbase = (size_t)base * 4 + lane;
        size_t rmax  = (size_t)E * 4 - 1;
        if (rbase > rmax) rbase = rmax;
        float2 rv = __ldg((const float2*)radial + rbase);
        float rvx = rv.x, rvy = rv.y;

        int eb = (lane >> 3) * 4;
        float t0 = 0.f, t1 = 0.f;
        #pragma unroll
        for (int i = 0; i < 8; ++i) {
            int sl = eb + (i >> 1);
            float r0 = (i & 1) ? __shfl_sync(0xffffffffu, rvy, sl)
                               : __shfl_sync(0xffffffffu, rvx, sl);
            float r1 = (i & 1) ? __shfl_sync(0xffffffffu, rvy, sl + 16)
                               : __shfl_sync(0xffffffffu, rvx, sl + 16);
            t0 = fmaf(r0, wr1r[i], t0);
            t1 = fmaf(r1, wr1r[i], t1);
        }
        // h[e][q] lives at sm_h[e*8+q]: h0 covers lanes 0..31 (e 0-3),
        // h1 covers +32 (e 4-7)
        sm_h[wib][lane]      = silu_f(t0 * inv_sqrt8);
        sm_h[wib][32 + lane] = silu_f(t1 * inv_sqrt8);
        if (lane < 8) {
            sm_ix[wib][lane * 2]     = snd8;
            sm_ix[wib][lane * 2 + 1] = rcv8;
        }
    }
    __syncwarp();

    #pragma unroll
    for (int j = 0; j < 8; ++j) {
        bool vj = (base + j) < E;
        int2 ix = *(const int2*)&sm_ix[wib][j * 2];   // uniform LDS.64
        int snd = ix.x, rcv = ix.y;

        float4 ha = *(const float4*)&sm_h[wib][j * 8];      // h[j][0..3]
        float4 hb = *(const float4*)&sm_h[wib][j * 8 + 4];  // h[j][4..7]
        float hv[8] = {ha.x, ha.y, ha.z, ha.w, hb.x, hb.y, hb.z, hb.w};

        u64 w01 = zero2, w23 = zero2;
        #pragma unroll
        for (int q = 0; q < 8; ++q) {
            u64 h2 = pack2(hv[q], hv[q]);
            w01 = fma2(h2, wr2p0[q], w01);
            w23 = fma2(h2, wr2p1[q], w23);
        }
        w01 = mul2(w01, wk2);
        w23 = mul2(w23, wk2);
        float wA0, wA1, wA2, wA3;
        unpack2(w01, wA0, wA1);
        unpack2(w23, wA2, wA3);

        float wB0 = __shfl_sync(0xffffffffu, wA0, srcB);
        float wB1 = __shfl_sync(0xffffffffu, wA1, srcB);
        float wB2 = __shfl_sync(0xffffffffu, wA2, srcB);
        float wB3 = __shfl_sync(0xffffffffu, wA3, srcB);

        int ee = vj ? (base + j) : (E - 1);
        float4 sh = __ldg((const float4*)ef + ee);           // broadcast

        const float* sup_row = g_sup + (size_t)snd * 32 + cidx;
        const float* vup_row = g_vup + (size_t)snd * 96 + cidx;
        float4 q1 = __ldg((const float4*)(scalA ? sup_row : vup_row));        // se | ve0
        float4 q2 = __ldg((const float4*)(g3 ? vup_row + 64 : vup_row + 32)); // ve1 | ve2
        float4 q3 = __ldg((const float4*)(vup_row + 64));                     // ve2

        float d0 = fmaf(q3.x, sh.w, fmaf(q2.x, sh.z, q1.x * sh.y));
        float d1 = fmaf(q3.y, sh.w, fmaf(q2.y, sh.z, q1.y * sh.y));
        float d2 = fmaf(q3.z, sh.w, fmaf(q2.z, sh.z, q1.z * sh.y));
        float d3 = fmaf(q3.w, sh.w, fmaf(q2.w, sh.z, q1.w * sh.y));

        float sA = g1 ? inv_sqrt3 : (g2 ? sh.y : sh.x);
        float sB = g0 ? sh.z : (g2 ? sh.w : sh.x);

        float bA0 = g1 ? d0 : q1.x;
        float bA1 = g1 ? d1 : q1.y;
        float bA2 = g1 ? d2 : q1.z;
        float bA3 = g1 ? d3 : q1.w;

        float bB0 = scalA ? q1.x : q2.x;
        float bB1 = scalA ? q1.y : q2.y;
        float bB2 = scalA ? q1.z : q2.z;
        float bB3 = scalA ? q1.w : q2.w;

        float* dst = g_agg + (size_t)rcv * 256 + loff;
        if (vj) {
            red_add_v4(dst,
                       (wA0 * sA) * bA0, (wA1 * sA) * bA1,
                       (wA2 * sA) * bA2, (wA3 * sA) * bA3);
            red_add_v4(dst + 128,
                       (wB0 * sB) * bB0, (wB1 * sB) * bB1,
                       (wB2 * sB) * bB2, (wB3 * sB) * bB3);
        }
    }
}

// ---------------------------------------------------------------------------
// Kernel C: down-projection + skip + gated output, 4 nodes/warp.
// Round-14 change: SHUFFLE-FREE. Broadcast operands read directly from
// g_agg via uniform LDG.128 (the [slot][c] layout is c-contiguous), 4 c's
// per load: 1024 shfl/warp -> 256 uniform loads/warp.
// ---------------------------------------------------------------------------
__global__ void __launch_bounds__(256) node_down_kernel(
    const float* __restrict__ Wds,  // (64,64)
    const float* __restrict__ Wdv,  // (64,32)
    float* __restrict__ out,
    int N)
{
    int warp = (blockIdx.x * blockDim.x + threadIdx.x) >> 5;
    int lane = threadIdx.x & 31;
    int n0 = warp * 4;
    if (n0 >= N) return;

    const float* ag[4];
    #pragma unroll
    for (int k = 0; k < 4; ++k) {
        int n = n0 + k; if (n > N - 1) n = N - 1;
        ag[k] = g_agg + (size_t)n * 256;
    }

    float sc0[4] = {0.f, 0.f, 0.f, 0.f}, sc1[4] = {0.f, 0.f, 0.f, 0.f};
    float vc0[4] = {0.f, 0.f, 0.f, 0.f}, vc1[4] = {0.f, 0.f, 0.f, 0.f};
    float vc2[4] = {0.f, 0.f, 0.f, 0.f};

    #pragma unroll 2
    for (int cg = 0; cg < 8; ++cg) {
        // weights for c = 4*cg .. 4*cg+3 (this lane's output column)
        float wsa[4], wsb[4], wsa2[4], wsb2[4], wv0[4], wv1[4];
        #pragma unroll
        for (int i = 0; i < 4; ++i) {
            int c = cg * 4 + i;
            wsa[i]  = __ldg(Wds + c * 64 + lane);
            wsb[i]  = __ldg(Wds + (32 + c) * 64 + lane);
            wsa2[i] = __ldg(Wds + c * 64 + 32 + lane);
            wsb2[i] = __ldg(Wds + (32 + c) * 64 + 32 + lane);
            wv0[i]  = __ldg(Wdv + c * 32 + lane);
            wv1[i]  = __ldg(Wdv + (32 + c) * 32 + lane);
        }
        #pragma unroll
        for (int k = 0; k < 4; ++k) {
            const float* a = ag[k] + cg * 4;
            float4 A0 = __ldg((const float4*)(a));        // a0  low  c..c+3
            float4 A1 = __ldg((const float4*)(a + 32));   // a0  high
            float4 B0 = __ldg((const float4*)(a + 64));   // a1 x=0 low
            float4 B1 = __ldg((const float4*)(a + 96));   // a1 x=0 high
            float4 C0 = __ldg((const float4*)(a + 128));  // a1 x=1 low
            float4 C1 = __ldg((const float4*)(a + 160));  // a1 x=1 high
            float4 D0 = __ldg((const float4*)(a + 192));  // a1 x=2 low
            float4 D1 = __ldg((const float4*)(a + 224));  // a1 x=2 high

            float a0l[4] = {A0.x, A0.y, A0.z, A0.w};
            float a0h[4] = {A1.x, A1.y, A1.z, A1.w};
            float b0[4]  = {B0.x, B0.y, B0.z, B0.w};
            float b1[4]  = {B1.x, B1.y, B1.z, B1.w};
            float c0[4]  = {C0.x, C0.y, C0.z, C0.w};
            float c1[4]  = {C1.x, C1.y, C1.z, C1.w};
            float e0[4]  = {D0.x, D0.y, D0.z, D0.w};
            float e1[4]  = {D1.x, D1.y, D1.z, D1.w};

            #pragma unroll
            for (int i = 0; i < 4; ++i) {
                sc0[k] = fmaf(a0l[i], wsa[i],  sc0[k]);
                sc0[k] = fmaf(a0h[i], wsb[i],  sc0[k]);
                sc1[k] = fmaf(a0l[i], wsa2[i], sc1[k]);
                sc1[k] = fmaf(a0h[i], wsb2[i], sc1[k]);
                vc0[k] = fmaf(b0[i], wv0[i], vc0[k]);
                vc0[k] = fmaf(b1[i], wv1[i], vc0[k]);
                vc1[k] = fmaf(c0[i], wv0[i], vc1[k]);
                vc1[k] = fmaf(c1[i], wv1[i], vc1[k]);
                vc2[k] = fmaf(e0[i], wv0[i], vc2[k]);
                vc2[k] = fmaf(e1[i], wv1[i], vc2[k]);
            }
        }
    }

    const float i2c = 0.125f; // 1/sqrt(64)
    #pragma unroll
    for (int k = 0; k < 4; ++k) {
        int n = n0 + k;
        if (n >= N) break;
        float scl = 0.5f * (sc0[k] * i2c + g_skip_s[n * 64 + lane]);
        float sch = 0.5f * (sc1[k] * i2c + g_skip_s[n * 64 + 32 + lane]);
        float feat = silu_f(scl);
        float gate = silu_f(sch);

        float vg0 = 0.5f * (vc0[k] * i2c + g_skip_v[n * 96 +      lane]) * gate;
        float vg1 = 0.5f * (vc1[k] * i2c + g_skip_v[n * 96 + 32 + lane]) * gate;
        float vg2 = 0.5f * (vc2[k] * i2c + g_skip_v[n * 96 + 64 + lane]) * gate;

        float* o = out + (size_t)n * 128;
        o[lane] = feat;
        o[32 + 3 * lane + 0] = vg0;
        o[32 + 3 * lane + 1] = vg1;
        o[32 + 3 * lane + 2] = vg2;
    }
}

// ---------------------------------------------------------------------------
extern "C" void kernel_launch(void* const* d_in, const int* in_sizes, int n_in,
                              void* d_out, int out_size)
{
    const float* nf      = (const float*)d_in[0];
    const float* ef      = (const float*)d_in[1];
    const float* radial  = (const float*)d_in[2];
    const int*   snd     = (const int*)  d_in[3];
    const int*   rcv     = (const int*)  d_in[4];
    const int*   species = (const int*)  d_in[5];
    const float* Wus     = (const float*)d_in[6];
    const float* Wuv     = (const float*)d_in[7];
    const float* Wr1     = (const float*)d_in[8];
    const float* Wr2     = (const float*)d_in[9];
    const float* Wds     = (const float*)d_in[10];
    const float* Wdv     = (const float*)d_in[11];
    const float* Wss     = (const float*)d_in[12];
    const float* Wsv     = (const float*)d_in[13];
    float* out = (float*)d_out;

    int N = in_sizes[0] / 128;
    int E = in_sizes[3];

    int ewarps  = (E + 7) / 8;
    int eblocks = (ewarps + 7) / 8;
    int dwarps  = (N + 3) / 4;
    int dblocks = (dwarps + 7) / 8;

    node_up_kernel  <<<(N + 7) / 8, 256>>>(nf, species, Wus, Wuv, Wss, Wsv, N);
    edge_kernel     <<<eblocks, 256>>>(ef, radial, snd, rcv, Wr1, Wr2, E);
    node_down_kernel<<<dblocks, 256>>>(Wds, Wdv, out, N);
}

// round 15
// speedup vs baseline: 1.0256x; 1.0256x over previous
#include <cuda_runtime.h>

// Problem constants (fixed by the dataset)
#define MAXN 50000
#define MAXE 800000

typedef unsigned long long u64;

// Persistent device scratch (allocation-free rule: __device__ globals)
static __device__ __align__(16) float g_sup[MAXN * 32];     // s_up   [n][c]
static __device__ __align__(16) float g_vup[MAXN * 96];     // v_up   [n][x][c]
static __device__ __align__(16) float g_skip_s[MAXN * 64];  // skip_s [n][d]
static __device__ __align__(16) float g_skip_v[MAXN * 96];  // skip_v [n][x][c]
static __device__ __align__(16) float g_agg[MAXN * 256];    // [n][slot][c]

__device__ __forceinline__ float silu_f(float x) {
    return x / (1.0f + __expf(-x));
}

__device__ __forceinline__ void red_add_v4(float* p, float a, float b, float c, float d) {
    asm volatile("red.global.add.v4.f32 [%0], {%1,%2,%3,%4};"
                 :: "l"(p), "f"(a), "f"(b), "f"(c), "f"(d)
                 : "memory");
}

// ---- packed f32x2 helpers (Blackwell FFMA2 path) ----
__device__ __forceinline__ u64 pack2(float lo, float hi) {
    u64 r; asm("mov.b64 %0, {%1, %2};" : "=l"(r) : "f"(lo), "f"(hi)); return r;
}
__device__ __forceinline__ void unpack2(u64 p, float& lo, float& hi) {
    asm("mov.b64 {%0, %1}, %2;" : "=f"(lo), "=f"(hi) : "l"(p));
}
__device__ __forceinline__ u64 fma2(u64 a, u64 b, u64 c) {
    u64 d; asm("fma.rn.f32x2 %0, %1, %2, %3;" : "=l"(d) : "l"(a), "l"(b), "l"(c)); return d;
}
__device__ __forceinline__ u64 mul2(u64 a, u64 b) {
    u64 d; asm("mul.rn.f32x2 %0, %1, %2;" : "=l"(d) : "l"(a), "l"(b)); return d;
}

// ---------------------------------------------------------------------------
// Kernel A: per-node up-projection + species skip (round-1 champion,
// UNCHANGED; also zeroes this node's agg slab).
// ---------------------------------------------------------------------------
__global__ void node_up_kernel(const float* __restrict__ nf,
                               const int*   __restrict__ species,
                               const float* __restrict__ Wus,   // (32,32)
                               const float* __restrict__ Wuv,   // (32,32)
                               const float* __restrict__ Wss,   // (5,32,64)
                               const float* __restrict__ Wsv,   // (5,32,32)
                               int N)
{
    int warp = (blockIdx.x * blockDim.x + threadIdx.x) >> 5;
    int lane = threadIdx.x & 31;
    if (warp >= N) return;
    int n = warp;

    const float* nfp = nf + (size_t)n * 128;
    float s  = nfp[lane];
    float v0 = nfp[32 + lane * 3 + 0];
    float v1 = nfp[32 + lane * 3 + 1];
    float v2 = nfp[32 + lane * 3 + 2];
    int sp = species[n];
    const float* wss = Wss + sp * 2048;
    const float* wsv = Wsv + sp * 1024;

    float sup = 0.f, vu0 = 0.f, vu1 = 0.f, vu2 = 0.f;
    float ss0 = 0.f, ss1 = 0.f, sv0 = 0.f, sv1 = 0.f, sv2 = 0.f;

    #pragma unroll
    for (int c = 0; c < 32; ++c) {
        float sb = __shfl_sync(0xffffffffu, s,  c);
        float b0 = __shfl_sync(0xffffffffu, v0, c);
        float b1 = __shfl_sync(0xffffffffu, v1, c);
        float b2 = __shfl_sync(0xffffffffu, v2, c);
        sup = fmaf(sb, __ldg(Wus + c * 32 + lane), sup);
        float wu = __ldg(Wuv + c * 32 + lane);
        vu0 = fmaf(b0, wu, vu0);
        vu1 = fmaf(b1, wu, vu1);
        vu2 = fmaf(b2, wu, vu2);
        ss0 = fmaf(sb, __ldg(wss + c * 64 + lane), ss0);
        ss1 = fmaf(sb, __ldg(wss + c * 64 + 32 + lane), ss1);
        float wv = __ldg(wsv + c * 32 + lane);
        sv0 = fmaf(b0, wv, sv0);
        sv1 = fmaf(b1, wv, sv1);
        sv2 = fmaf(b2, wv, sv2);
    }

    const float isc = 0.17677669529663687f; // 1/sqrt(32)
    g_sup[n * 32 + lane]             = sup * isc;
    g_vup[n * 96 + 0 * 32 + lane]    = vu0 * isc;
    g_vup[n * 96 + 1 * 32 + lane]    = vu1 * isc;
    g_vup[n * 96 + 2 * 32 + lane]    = vu2 * isc;
    g_skip_s[n * 64 + lane]          = ss0 * isc;
    g_skip_s[n * 64 + 32 + lane]     = ss1 * isc;
    g_skip_v[n * 96 + 0 * 32 + lane] = sv0 * isc;
    g_skip_v[n * 96 + 1 * 32 + lane] = sv1 * isc;
    g_skip_v[n * 96 + 2 * 32 + lane] = sv2 * isc;

    #pragma unroll
    for (int k = 0; k < 2; ++k)
        *(float4*)(g_agg + n * 256 + (k * 32 + lane) * 4) = make_float4(0.f, 0.f, 0.f, 0.f);
}

// ---------------------------------------------------------------------------
// Kernel B: edge kernel (EXACT round-11 champion, UNCHANGED).
// ---------------------------------------------------------------------------
__global__ void __launch_bounds__(256, 3) edge_kernel(
    const float* __restrict__ ef,
    const float* __restrict__ radial,
    const int*   __restrict__ snd_,
    const int*   __restrict__ rcv_,
    const float* __restrict__ Wr1,   // (8,8)
    const float* __restrict__ Wr2,   // (8,128)
    int E)
{
    int warp = (blockIdx.x * blockDim.x + threadIdx.x) >> 5;
    int lane = threadIdx.x & 31;
    int base = warp * 8;
    if (base >= E) return;

    const float inv_sqrt8 = 0.35355339059327373f;
    const float inv_sqrt3 = 0.5773502691896258f;
    const float wk        = 0.08838834764831845f; // inv_sqrt8 * 1/sqrt(16)

    int grp  = lane >> 3;
    int pA   = (grp == 0) ? 0 : ((grp == 1) ? 3 : ((grp == 2) ? 1 : 2));
    int srcB = (grp < 2) ? lane + 16 : lane;
    int cidx = (lane & 7) * 4;
    int jj   = lane & 7;
    int loff = (lane >> 4) * 64 + (lane & 15) * 4;

    bool g1 = (grp == 1), g2 = (grp == 2), g3 = (grp == 3);
    bool g0 = (grp == 0);
    bool scalA = ((grp & 1) == 0);

    float wr1r[8];
    #pragma unroll
    for (int i = 0; i < 8; ++i) wr1r[i] = __ldg(Wr1 + i * 8 + jj);

    int wcol = pA * 32 + cidx;
    u64 wr2p0[8], wr2p1[8];
    #pragma unroll
    for (int q = 0; q < 8; ++q) {
        float4 wr = __ldg((const float4*)(Wr2 + q * 128 + wcol));
        wr2p0[q] = pack2(wr.x, wr.y);
        wr2p1[q] = pack2(wr.z, wr.w);
    }
    u64 wk2   = pack2(wk, wk);
    u64 zero2 = pack2(0.f, 0.f);

    int eic = base + jj; if (eic > E - 1) eic = E - 1;
    int snd8 = __ldg(snd_ + eic);
    int rcv8 = __ldg(rcv_ + eic);

    size_t rbase = (size_t)base * 4 + lane;
    size_t rmax  = (size_t)E * 4 - 1;
    if (rbase > rmax) rbase = rmax;
    float2 rv = __ldg((const float2*)radial + rbase);
    float rvx = rv.x, rvy = rv.y;

    float h0, h1;
    {
        int eb = (lane >> 3) * 4;
        float t0 = 0.f, t1 = 0.f;
        #pragma unroll
        for (int i = 0; i < 8; ++i) {
            int sl = eb + (i >> 1);
            float r0 = (i & 1) ? __shfl_sync(0xffffffffu, rvy, sl)
                               : __shfl_sync(0xffffffffu, rvx, sl);
            float r1 = (i & 1) ? __shfl_sync(0xffffffffu, rvy, sl + 16)
                               : __shfl_sync(0xffffffffu, rvx, sl + 16);
            t0 = fmaf(r0, wr1r[i], t0);
            t1 = fmaf(r1, wr1r[i], t1);
        }
        h0 = silu_f(t0 * inv_sqrt8);
        h1 = silu_f(t1 * inv_sqrt8);
    }

    #pragma unroll
    for (int j = 0; j < 8; ++j) {
        bool vj = (base + j) < E;
        int snd = __shfl_sync(0xffffffffu, snd8, j);
        int rcv = __shfl_sync(0xffffffffu, rcv8, j);

        u64 w01 = zero2, w23 = zero2;
        #pragma unroll
        for (int q = 0; q < 8; ++q) {
            float hq = (j < 4) ? __shfl_sync(0xffffffffu, h0, (j & 3) * 8 + q)
                               : __shfl_sync(0xffffffffu, h1, (j & 3) * 8 + q);
            u64 h2 = pack2(hq, hq);
            w01 = fma2(h2, wr2p0[q], w01);
            w23 = fma2(h2, wr2p1[q], w23);
        }
        w01 = mul2(w01, wk2);
        w23 = mul2(w23, wk2);
        float wA0, wA1, wA2, wA3;
        unpack2(w01, wA0, wA1);
        unpack2(w23, wA2, wA3);

        float wB0 = __shfl_sync(0xffffffffu, wA0, srcB);
        float wB1 = __shfl_sync(0xffffffffu, wA1, srcB);
        float wB2 = __shfl_sync(0xffffffffu, wA2, srcB);
        float wB3 = __shfl_sync(0xffffffffu, wA3, srcB);

        int ee = vj ? (base + j) : (E - 1);
        float4 sh = __ldg((const float4*)ef + ee);           // broadcast

        const float* sup_row = g_sup + (size_t)snd * 32 + cidx;
        const float* vup_row = g_vup + (size_t)snd * 96 + cidx;
        float4 q1 = __ldg((const float4*)(scalA ? sup_row : vup_row));        // se | ve0
        float4 q2 = __ldg((const float4*)(g3 ? vup_row + 64 : vup_row + 32)); // ve1 | ve2
        float4 q3 = __ldg((const float4*)(vup_row + 64));                     // ve2

        float d0 = fmaf(q3.x, sh.w, fmaf(q2.x, sh.z, q1.x * sh.y));
        float d1 = fmaf(q3.y, sh.w, fmaf(q2.y, sh.z, q1.y * sh.y));
        float d2 = fmaf(q3.z, sh.w, fmaf(q2.z, sh.z, q1.z * sh.y));
        float d3 = fmaf(q3.w, sh.w, fmaf(q2.w, sh.z, q1.w * sh.y));

        float sA = g1 ? inv_sqrt3 : (g2 ? sh.y : sh.x);
        float sB = g0 ? sh.z : (g2 ? sh.w : sh.x);

        float bA0 = g1 ? d0 : q1.x;
        float bA1 = g1 ? d1 : q1.y;
        float bA2 = g1 ? d2 : q1.z;
        float bA3 = g1 ? d3 : q1.w;

        float bB0 = scalA ? q1.x : q2.x;
        float bB1 = scalA ? q1.y : q2.y;
        float bB2 = scalA ? q1.z : q2.z;
        float bB3 = scalA ? q1.w : q2.w;

        float* dst = g_agg + (size_t)rcv * 256 + loff;
        if (vj) {
            red_add_v4(dst,
                       (wA0 * sA) * bA0, (wA1 * sA) * bA1,
                       (wA2 * sA) * bA2, (wA3 * sA) * bA3);
            red_add_v4(dst + 128,
                       (wB0 * sB) * bB0, (wB1 * sB) * bB1,
                       (wB2 * sB) * bB2, (wB3 * sB) * bB3);
        }
    }
}

// ---------------------------------------------------------------------------
// Kernel C: down-projection + skip + gated output, 4 nodes/warp.
// Round-15 SINGLE CHANGE vs champion: shuffle-free broadcasts via uniform
// LDG.128 from g_agg, streamed SLOT-SEQUENTIALLY (2 float4 live at a time)
// to keep regs under the champion's 80. 1024 shfl/warp -> 256 uniform loads.
// ---------------------------------------------------------------------------
__global__ void __launch_bounds__(256) node_down_kernel(
    const float* __restrict__ Wds,  // (64,64)
    const float* __restrict__ Wdv,  // (64,32)
    float* __restrict__ out,
    int N)
{
    int warp = (blockIdx.x * blockDim.x + threadIdx.x) >> 5;
    int lane = threadIdx.x & 31;
    int n0 = warp * 4;
    if (n0 >= N) return;

    const float* ag[4];
    #pragma unroll
    for (int k = 0; k < 4; ++k) {
        int n = n0 + k; if (n > N - 1) n = N - 1;
        ag[k] = g_agg + (size_t)n * 256;
    }

    float sc0[4] = {0.f, 0.f, 0.f, 0.f}, sc1[4] = {0.f, 0.f, 0.f, 0.f};
    float vc0[4] = {0.f, 0.f, 0.f, 0.f}, vc1[4] = {0.f, 0.f, 0.f, 0.f};
    float vc2[4] = {0.f, 0.f, 0.f, 0.f};

    for (int cg = 0; cg < 8; ++cg) {
        // weights for c = 4*cg .. 4*cg+3 at this lane's output column
        float wsa[4], wsb[4], wsa2[4], wsb2[4], wv0[4], wv1[4];
        #pragma unroll
        for (int i = 0; i < 4; ++i) {
            int c = cg * 4 + i;
            wsa[i]  = __ldg(Wds + c * 64 + lane);
            wsb[i]  = __ldg(Wds + (32 + c) * 64 + lane);
            wsa2[i] = __ldg(Wds + c * 64 + 32 + lane);
            wsb2[i] = __ldg(Wds + (32 + c) * 64 + 32 + lane);
            wv0[i]  = __ldg(Wdv + c * 32 + lane);
            wv1[i]  = __ldg(Wdv + (32 + c) * 32 + lane);
        }
        #pragma unroll
        for (int k = 0; k < 4; ++k) {
            const float* a = ag[k] + cg * 4;
            // slot pair 0: scalar agg -> sc0, sc1
            {
                float4 L = __ldg((const float4*)(a));
                float4 H = __ldg((const float4*)(a + 32));
                sc0[k] = fmaf(L.x, wsa[0],  sc0[k]);
                sc0[k] = fmaf(L.y, wsa[1],  sc0[k]);
                sc0[k] = fmaf(L.z, wsa[2],  sc0[k]);
                sc0[k] = fmaf(L.w, wsa[3],  sc0[k]);
                sc0[k] = fmaf(H.x, wsb[0],  sc0[k]);
                sc0[k] = fmaf(H.y, wsb[1],  sc0[k]);
                sc0[k] = fmaf(H.z, wsb[2],  sc0[k]);
                sc0[k] = fmaf(H.w, wsb[3],  sc0[k]);
                sc1[k] = fmaf(L.x, wsa2[0], sc1[k]);
                sc1[k] = fmaf(L.y, wsa2[1], sc1[k]);
                sc1[k] = fmaf(L.z, wsa2[2], sc1[k]);
                sc1[k] = fmaf(L.w, wsa2[3], sc1[k]);
                sc1[k] = fmaf(H.x, wsb2[0], sc1[k]);
                sc1[k] = fmaf(H.y, wsb2[1], sc1[k]);
                sc1[k] = fmaf(H.z, wsb2[2], sc1[k]);
                sc1[k] = fmaf(H.w, wsb2[3], sc1[k]);
            }
            // slot pair 1: a1 x=0 -> vc0
            {
                float4 L = __ldg((const float4*)(a + 64));
                float4 H = __ldg((const float4*)(a + 96));
                vc0[k] = fmaf(L.x, wv0[0], vc0[k]);
                vc0[k] = fmaf(L.y, wv0[1], vc0[k]);
                vc0[k] = fmaf(L.z, wv0[2], vc0[k]);
                vc0[k] = fmaf(L.w, wv0[3], vc0[k]);
                vc0[k] = fmaf(H.x, wv1[0], vc0[k]);
                vc0[k] = fmaf(H.y, wv1[1], vc0[k]);
                vc0[k] = fmaf(H.z, wv1[2], vc0[k]);
                vc0[k] = fmaf(H.w, wv1[3], vc0[k]);
            }
            // slot pair 2: a1 x=1 -> vc1
            {
                float4 L = __ldg((const float4*)(a + 128));
                float4 H = __ldg((const float4*)(a + 160));
                vc1[k] = fmaf(L.x, wv0[0], vc1[k]);
                vc1[k] = fmaf(L.y, wv0[1], vc1[k]);
                vc1[k] = fmaf(L.z, wv0[2], vc1[k]);
                vc1[k] = fmaf(L.w, wv0[3], vc1[k]);
                vc1[k] = fmaf(H.x, wv1[0], vc1[k]);
                vc1[k] = fmaf(H.y, wv1[1], vc1[k]);
                vc1[k] = fmaf(H.z, wv1[2], vc1[k]);
                vc1[k] = fmaf(H.w, wv1[3], vc1[k]);
            }
            // slot pair 3: a1 x=2 -> vc2
            {
                float4 L = __ldg((const float4*)(a + 192));
                float4 H = __ldg((const float4*)(a + 224));
                vc2[k] = fmaf(L.x, wv0[0], vc2[k]);
                vc2[k] = fmaf(L.y, wv0[1], vc2[k]);
                vc2[k] = fmaf(L.z, wv0[2], vc2[k]);
                vc2[k] = fmaf(L.w, wv0[3], vc2[k]);
                vc2[k] = fmaf(H.x, wv1[0], vc2[k]);
                vc2[k] = fmaf(H.y, wv1[1], vc2[k]);
                vc2[k] = fmaf(H.z, wv1[2], vc2[k]);
                vc2[k] = fmaf(H.w, wv1[3], vc2[k]);
            }
        }
    }

    const float i2c = 0.125f; // 1/sqrt(64)
    #pragma unroll
    for (int k = 0; k < 4; ++k) {
        int n = n0 + k;
        if (n >= N) break;
        float scl = 0.5f * (sc0[k] * i2c + g_skip_s[n * 64 + lane]);
        float sch = 0.5f * (sc1[k] * i2c + g_skip_s[n * 64 + 32 + lane]);
        float feat = silu_f(scl);
        float gate = silu_f(sch);

        float vg0 = 0.5f * (vc0[k] * i2c + g_skip_v[n * 96 +      lane]) * gate;
        float vg1 = 0.5f * (vc1[k] * i2c + g_skip_v[n * 96 + 32 + lane]) * gate;
        float vg2 = 0.5f * (vc2[k] * i2c + g_skip_v[n * 96 + 64 + lane]) * gate;

        float* o = out + (size_t)n * 128;
        o[lane] = feat;
        o[32 + 3 * lane + 0] = vg0;
        o[32 + 3 * lane + 1] = vg1;
        o[32 + 3 * lane + 2] = vg2;
    }
}

// ---------------------------------------------------------------------------
extern "C" void kernel_launch(void* const* d_in, const int* in_sizes, int n_in,
                              void* d_out, int out_size)
{
    const float* nf      = (const float*)d_in[0];
    const float* ef      = (const float*)d_in[1];
    const float* radial  = (const float*)d_in[2];
    const int*   snd     = (const int*)  d_in[3];
    const int*   rcv     = (const int*)  d_in[4];
    const int*   species = (const int*)  d_in[5];
    const float* Wus     = (const float*)d_in[6];
    const float* Wuv     = (const float*)d_in[7];
    const float* Wr1     = (const float*)d_in[8];
    const float* Wr2     = (const float*)d_in[9];
    const float* Wds     = (const float*)d_in[10];
    const float* Wdv     = (const float*)d_in[11];
    const float* Wss     = (const float*)d_in[12];
    const float* Wsv     = (const float*)d_in[13];
    float* out = (float*)d_out;

    int N = in_sizes[0] / 128;
    int E = in_sizes[3];

    int ewarps  = (E + 7) / 8;
    int eblocks = (ewarps + 7) / 8;
    int dwarps  = (N + 3) / 4;
    int dblocks = (dwarps + 7) / 8;

    node_up_kernel  <<<(N + 7) / 8, 256>>>(nf, species, Wus, Wuv, Wss, Wsv, N);
    edge_kernel     <<<eblocks, 256>>>(ef, radial, snd, rcv, Wr1, Wr2, E);
    node_down_kernel<<<dblocks, 256>>>(Wds, Wdv, out, N);
}

// round 16
// speedup vs baseline: 1.1444x; 1.1159x over previous
#include <cuda_runtime.h>

// Problem constants (fixed by the dataset)
#define MAXN 50000
#define MAXE 800000

typedef unsigned long long u64;

// Persistent device scratch (allocation-free rule: __device__ globals)
static __device__ __align__(16) float g_sup[MAXN * 32];     // s_up   [n][c]
static __device__ __align__(16) float g_vup[MAXN * 96];     // v_up   [n][x][c]
static __device__ __align__(16) float g_skip_s[MAXN * 64];  // skip_s [n][d]
static __device__ __align__(16) float g_skip_v[MAXN * 96];  // skip_v [n][x][c]
static __device__ __align__(16) float g_agg[MAXN * 256];    // [n][slot][c]

__device__ __forceinline__ float silu_f(float x) {
    return x / (1.0f + __expf(-x));
}

__device__ __forceinline__ void red_add_v4(float* p, float a, float b, float c, float d) {
    asm volatile("red.global.add.v4.f32 [%0], {%1,%2,%3,%4};"
                 :: "l"(p), "f"(a), "f"(b), "f"(c), "f"(d)
                 : "memory");
}

// ---- packed f32x2 helpers (Blackwell FFMA2 path) ----
__device__ __forceinline__ u64 pack2(float lo, float hi) {
    u64 r; asm("mov.b64 %0, {%1, %2};" : "=l"(r) : "f"(lo), "f"(hi)); return r;
}
__device__ __forceinline__ void unpack2(u64 p, float& lo, float& hi) {
    asm("mov.b64 {%0, %1}, %2;" : "=f"(lo), "=f"(hi) : "l"(p));
}
__device__ __forceinline__ u64 fma2(u64 a, u64 b, u64 c) {
    u64 d; asm("fma.rn.f32x2 %0, %1, %2, %3;" : "=l"(d) : "l"(a), "l"(b), "l"(c)); return d;
}
__device__ __forceinline__ u64 mul2(u64 a, u64 b) {
    u64 d; asm("mul.rn.f32x2 %0, %1, %2;" : "=l"(d) : "l"(a), "l"(b)); return d;
}

// ---------------------------------------------------------------------------
// Kernel A: per-node up-projection + species skip (round-1 champion,
// UNCHANGED; also zeroes this node's agg slab).
// ---------------------------------------------------------------------------
__global__ void node_up_kernel(const float* __restrict__ nf,
                               const int*   __restrict__ species,
                               const float* __restrict__ Wus,   // (32,32)
                               const float* __restrict__ Wuv,   // (32,32)
                               const float* __restrict__ Wss,   // (5,32,64)
                               const float* __restrict__ Wsv,   // (5,32,32)
                               int N)
{
    int warp = (blockIdx.x * blockDim.x + threadIdx.x) >> 5;
    int lane = threadIdx.x & 31;
    if (warp >= N) return;
    int n = warp;

    const float* nfp = nf + (size_t)n * 128;
    float s  = nfp[lane];
    float v0 = nfp[32 + lane * 3 + 0];
    float v1 = nfp[32 + lane * 3 + 1];
    float v2 = nfp[32 + lane * 3 + 2];
    int sp = species[n];
    const float* wss = Wss + sp * 2048;
    const float* wsv = Wsv + sp * 1024;

    float sup = 0.f, vu0 = 0.f, vu1 = 0.f, vu2 = 0.f;
    float ss0 = 0.f, ss1 = 0.f, sv0 = 0.f, sv1 = 0.f, sv2 = 0.f;

    #pragma unroll
    for (int c = 0; c < 32; ++c) {
        float sb = __shfl_sync(0xffffffffu, s,  c);
        float b0 = __shfl_sync(0xffffffffu, v0, c);
        float b1 = __shfl_sync(0xffffffffu, v1, c);
        float b2 = __shfl_sync(0xffffffffu, v2, c);
        sup = fmaf(sb, __ldg(Wus + c * 32 + lane), sup);
        float wu = __ldg(Wuv + c * 32 + lane);
        vu0 = fmaf(b0, wu, vu0);
        vu1 = fmaf(b1, wu, vu1);
        vu2 = fmaf(b2, wu, vu2);
        ss0 = fmaf(sb, __ldg(wss + c * 64 + lane), ss0);
        ss1 = fmaf(sb, __ldg(wss + c * 64 + 32 + lane), ss1);
        float wv = __ldg(wsv + c * 32 + lane);
        sv0 = fmaf(b0, wv, sv0);
        sv1 = fmaf(b1, wv, sv1);
        sv2 = fmaf(b2, wv, sv2);
    }

    const float isc = 0.17677669529663687f; // 1/sqrt(32)
    g_sup[n * 32 + lane]             = sup * isc;
    g_vup[n * 96 + 0 * 32 + lane]    = vu0 * isc;
    g_vup[n * 96 + 1 * 32 + lane]    = vu1 * isc;
    g_vup[n * 96 + 2 * 32 + lane]    = vu2 * isc;
    g_skip_s[n * 64 + lane]          = ss0 * isc;
    g_skip_s[n * 64 + 32 + lane]     = ss1 * isc;
    g_skip_v[n * 96 + 0 * 32 + lane] = sv0 * isc;
    g_skip_v[n * 96 + 1 * 32 + lane] = sv1 * isc;
    g_skip_v[n * 96 + 2 * 32 + lane] = sv2 * isc;

    #pragma unroll
    for (int k = 0; k < 2; ++k)
        *(float4*)(g_agg + n * 256 + (k * 32 + lane) * 4) = make_float4(0.f, 0.f, 0.f, 0.f);
}

// ---------------------------------------------------------------------------
// Kernel B: edge kernel (EXACT round-11 champion, UNCHANGED).
// ---------------------------------------------------------------------------
__global__ void __launch_bounds__(256, 3) edge_kernel(
    const float* __restrict__ ef,
    const float* __restrict__ radial,
    const int*   __restrict__ snd_,
    const int*   __restrict__ rcv_,
    const float* __restrict__ Wr1,   // (8,8)
    const float* __restrict__ Wr2,   // (8,128)
    int E)
{
    int warp = (blockIdx.x * blockDim.x + threadIdx.x) >> 5;
    int lane = threadIdx.x & 31;
    int base = warp * 8;
    if (base >= E) return;

    const float inv_sqrt8 = 0.35355339059327373f;
    const float inv_sqrt3 = 0.5773502691896258f;
    const float wk        = 0.08838834764831845f; // inv_sqrt8 * 1/sqrt(16)

    int grp  = lane >> 3;
    int pA   = (grp == 0) ? 0 : ((grp == 1) ? 3 : ((grp == 2) ? 1 : 2));
    int srcB = (grp < 2) ? lane + 16 : lane;
    int cidx = (lane & 7) * 4;
    int jj   = lane & 7;
    int loff = (lane >> 4) * 64 + (lane & 15) * 4;

    bool g1 = (grp == 1), g2 = (grp == 2), g3 = (grp == 3);
    bool g0 = (grp == 0);
    bool scalA = ((grp & 1) == 0);

    float wr1r[8];
    #pragma unroll
    for (int i = 0; i < 8; ++i) wr1r[i] = __ldg(Wr1 + i * 8 + jj);

    int wcol = pA * 32 + cidx;
    u64 wr2p0[8], wr2p1[8];
    #pragma unroll
    for (int q = 0; q < 8; ++q) {
        float4 wr = __ldg((const float4*)(Wr2 + q * 128 + wcol));
        wr2p0[q] = pack2(wr.x, wr.y);
        wr2p1[q] = pack2(wr.z, wr.w);
    }
    u64 wk2   = pack2(wk, wk);
    u64 zero2 = pack2(0.f, 0.f);

    int eic = base + jj; if (eic > E - 1) eic = E - 1;
    int snd8 = __ldg(snd_ + eic);
    int rcv8 = __ldg(rcv_ + eic);

    size_t rbase = (size_t)base * 4 + lane;
    size_t rmax  = (size_t)E * 4 - 1;
    if (rbase > rmax) rbase = rmax;
    float2 rv = __ldg((const float2*)radial + rbase);
    float rvx = rv.x, rvy = rv.y;

    float h0, h1;
    {
        int eb = (lane >> 3) * 4;
        float t0 = 0.f, t1 = 0.f;
        #pragma unroll
        for (int i = 0; i < 8; ++i) {
            int sl = eb + (i >> 1);
            float r0 = (i & 1) ? __shfl_sync(0xffffffffu, rvy, sl)
                               : __shfl_sync(0xffffffffu, rvx, sl);
            float r1 = (i & 1) ? __shfl_sync(0xffffffffu, rvy, sl + 16)
                               : __shfl_sync(0xffffffffu, rvx, sl + 16);
            t0 = fmaf(r0, wr1r[i], t0);
            t1 = fmaf(r1, wr1r[i], t1);
        }
        h0 = silu_f(t0 * inv_sqrt8);
        h1 = silu_f(t1 * inv_sqrt8);
    }

    #pragma unroll
    for (int j = 0; j < 8; ++j) {
        bool vj = (base + j) < E;
        int snd = __shfl_sync(0xffffffffu, snd8, j);
        int rcv = __shfl_sync(0xffffffffu, rcv8, j);

        u64 w01 = zero2, w23 = zero2;
        #pragma unroll
        for (int q = 0; q < 8; ++q) {
            float hq = (j < 4) ? __shfl_sync(0xffffffffu, h0, (j & 3) * 8 + q)
                               : __shfl_sync(0xffffffffu, h1, (j & 3) * 8 + q);
            u64 h2 = pack2(hq, hq);
            w01 = fma2(h2, wr2p0[q], w01);
            w23 = fma2(h2, wr2p1[q], w23);
        }
        w01 = mul2(w01, wk2);
        w23 = mul2(w23, wk2);
        float wA0, wA1, wA2, wA3;
        unpack2(w01, wA0, wA1);
        unpack2(w23, wA2, wA3);

        float wB0 = __shfl_sync(0xffffffffu, wA0, srcB);
        float wB1 = __shfl_sync(0xffffffffu, wA1, srcB);
        float wB2 = __shfl_sync(0xffffffffu, wA2, srcB);
        float wB3 = __shfl_sync(0xffffffffu, wA3, srcB);

        int ee = vj ? (base + j) : (E - 1);
        float4 sh = __ldg((const float4*)ef + ee);           // broadcast

        const float* sup_row = g_sup + (size_t)snd * 32 + cidx;
        const float* vup_row = g_vup + (size_t)snd * 96 + cidx;
        float4 q1 = __ldg((const float4*)(scalA ? sup_row : vup_row));        // se | ve0
        float4 q2 = __ldg((const float4*)(g3 ? vup_row + 64 : vup_row + 32)); // ve1 | ve2
        float4 q3 = __ldg((const float4*)(vup_row + 64));                     // ve2

        float d0 = fmaf(q3.x, sh.w, fmaf(q2.x, sh.z, q1.x * sh.y));
        float d1 = fmaf(q3.y, sh.w, fmaf(q2.y, sh.z, q1.y * sh.y));
        float d2 = fmaf(q3.z, sh.w, fmaf(q2.z, sh.z, q1.z * sh.y));
        float d3 = fmaf(q3.w, sh.w, fmaf(q2.w, sh.z, q1.w * sh.y));

        float sA = g1 ? inv_sqrt3 : (g2 ? sh.y : sh.x);
        float sB = g0 ? sh.z : (g2 ? sh.w : sh.x);

        float bA0 = g1 ? d0 : q1.x;
        float bA1 = g1 ? d1 : q1.y;
        float bA2 = g1 ? d2 : q1.z;
        float bA3 = g1 ? d3 : q1.w;

        float bB0 = scalA ? q1.x : q2.x;
        float bB1 = scalA ? q1.y : q2.y;
        float bB2 = scalA ? q1.z : q2.z;
        float bB3 = scalA ? q1.w : q2.w;

        float* dst = g_agg + (size_t)rcv * 256 + loff;
        if (vj) {
            red_add_v4(dst,
                       (wA0 * sA) * bA0, (wA1 * sA) * bA1,
                       (wA2 * sA) * bA2, (wA3 * sA) * bA3);
            red_add_v4(dst + 128,
                       (wB0 * sB) * bB0, (wB1 * sB) * bB1,
                       (wB2 * sB) * bB2, (wB3 * sB) * bB3);
        }
    }
}

// ---------------------------------------------------------------------------
// Kernel C: down-projection + skip + gated output, 4 nodes/warp.
// Round-16 SINGLE CHANGE vs champion: broadcasts via uniform LDS.128 from a
// per-warp SMEM stage of g_agg (29-cyc tier, not the 234-cyc L2 tier that
// sank round 15). 1024 SHFL -> 256 uniform LDS.128 + 16 LDG.128 + 16 STS.128.
// Register pressure drops (no 32-reg a-prefetch) -> occupancy rises.
// ---------------------------------------------------------------------------
__global__ void __launch_bounds__(256) node_down_kernel(
    const float* __restrict__ Wds,  // (64,64)
    const float* __restrict__ Wdv,  // (64,32)
    float* __restrict__ out,
    int N)
{
    __shared__ __align__(16) float sm[8][1024];   // [warp][node*256 + slot*32 + c]

    int warp = (blockIdx.x * blockDim.x + threadIdx.x) >> 5;
    int wib  = (threadIdx.x >> 5) & 7;
    int lane = threadIdx.x & 31;
    int n0 = warp * 4;
    if (n0 >= N) return;

    // ---- stage 4 nodes' agg slabs into smem (coalesced LDG.128/STS.128) ----
    #pragma unroll
    for (int k = 0; k < 4; ++k) {
        int n = n0 + k; if (n > N - 1) n = N - 1;
        const float4* src = (const float4*)(g_agg + (size_t)n * 256);
        float4 x0 = __ldg(src + lane);         // floats [lane*4 .. +3]
        float4 x1 = __ldg(src + 32 + lane);    // floats [128 + lane*4 .. +3]
        *(float4*)&sm[wib][k * 256 + lane * 4]       = x0;
        *(float4*)&sm[wib][k * 256 + 128 + lane * 4] = x1;
    }
    __syncwarp();

    float sc0[4] = {0.f, 0.f, 0.f, 0.f}, sc1[4] = {0.f, 0.f, 0.f, 0.f};
    float vc0[4] = {0.f, 0.f, 0.f, 0.f}, vc1[4] = {0.f, 0.f, 0.f, 0.f};
    float vc2[4] = {0.f, 0.f, 0.f, 0.f};

    for (int cg = 0; cg < 8; ++cg) {
        // weights for c = 4*cg .. 4*cg+3 at this lane's output column
        float wsa[4], wsb[4], wsa2[4], wsb2[4], wv0[4], wv1[4];
        #pragma unroll
        for (int i = 0; i < 4; ++i) {
            int c = cg * 4 + i;
            wsa[i]  = __ldg(Wds + c * 64 + lane);
            wsb[i]  = __ldg(Wds + (32 + c) * 64 + lane);
            wsa2[i] = __ldg(Wds + c * 64 + 32 + lane);
            wsb2[i] = __ldg(Wds + (32 + c) * 64 + 32 + lane);
            wv0[i]  = __ldg(Wdv + c * 32 + lane);
            wv1[i]  = __ldg(Wdv + (32 + c) * 32 + lane);
        }
        #pragma unroll
        for (int k = 0; k < 4; ++k) {
            const float* a = &sm[wib][k * 256 + cg * 4];
            // slot pair 0: scalar agg -> sc0, sc1
            {
                float4 L = *(const float4*)(a);
                float4 H = *(const float4*)(a + 32);
                sc0[k] = fmaf(L.x, wsa[0],  sc0[k]);
                sc0[k] = fmaf(L.y, wsa[1],  sc0[k]);
                sc0[k] = fmaf(L.z, wsa[2],  sc0[k]);
                sc0[k] = fmaf(L.w, wsa[3],  sc0[k]);
                sc0[k] = fmaf(H.x, wsb[0],  sc0[k]);
                sc0[k] = fmaf(H.y, wsb[1],  sc0[k]);
                sc0[k] = fmaf(H.z, wsb[2],  sc0[k]);
                sc0[k] = fmaf(H.w, wsb[3],  sc0[k]);
                sc1[k] = fmaf(L.x, wsa2[0], sc1[k]);
                sc1[k] = fmaf(L.y, wsa2[1], sc1[k]);
                sc1[k] = fmaf(L.z, wsa2[2], sc1[k]);
                sc1[k] = fmaf(L.w, wsa2[3], sc1[k]);
                sc1[k] = fmaf(H.x, wsb2[0], sc1[k]);
                sc1[k] = fmaf(H.y, wsb2[1], sc1[k]);
                sc1[k] = fmaf(H.z, wsb2[2], sc1[k]);
                sc1[k] = fmaf(H.w, wsb2[3], sc1[k]);
            }
            // slot pair 1: a1 x=0 -> vc0
            {
                float4 L = *(const float4*)(a + 64);
                float4 H = *(const float4*)(a + 96);
                vc0[k] = fmaf(L.x, wv0[0], vc0[k]);
                vc0[k] = fmaf(L.y, wv0[1], vc0[k]);
                vc0[k] = fmaf(L.z, wv0[2], vc0[k]);
                vc0[k] = fmaf(L.w, wv0[3], vc0[k]);
                vc0[k] = fmaf(H.x, wv1[0], vc0[k]);
                vc0[k] = fmaf(H.y, wv1[1], vc0[k]);
                vc0[k] = fmaf(H.z, wv1[2], vc0[k]);
                vc0[k] = fmaf(H.w, wv1[3], vc0[k]);
            }
            // slot pair 2: a1 x=1 -> vc1
            {
                float4 L = *(const float4*)(a + 128);
                float4 H = *(const float4*)(a + 160);
                vc1[k] = fmaf(L.x, wv0[0], vc1[k]);
                vc1[k] = fmaf(L.y, wv0[1], vc1[k]);
                vc1[k] = fmaf(L.z, wv0[2], vc1[k]);
                vc1[k] = fmaf(L.w, wv0[3], vc1[k]);
                vc1[k] = fmaf(H.x, wv1[0], vc1[k]);
                vc1[k] = fmaf(H.y, wv1[1], vc1[k]);
                vc1[k] = fmaf(H.z, wv1[2], vc1[k]);
                vc1[k] = fmaf(H.w, wv1[3], vc1[k]);
            }
            // slot pair 3: a1 x=2 -> vc2
            {
                float4 L = *(const float4*)(a + 192);
                float4 H = *(const float4*)(a + 224);
                vc2[k] = fmaf(L.x, wv0[0], vc2[k]);
                vc2[k] = fmaf(L.y, wv0[1], vc2[k]);
                vc2[k] = fmaf(L.z, wv0[2], vc2[k]);
                vc2[k] = fmaf(L.w, wv0[3], vc2[k]);
                vc2[k] = fmaf(H.x, wv1[0], vc2[k]);
                vc2[k] = fmaf(H.y, wv1[1], vc2[k]);
                vc2[k] = fmaf(H.z, wv1[2], vc2[k]);
                vc2[k] = fmaf(H.w, wv1[3], vc2[k]);
            }
        }
    }

    const float i2c = 0.125f; // 1/sqrt(64)
    #pragma unroll
    for (int k = 0; k < 4; ++k) {
        int n = n0 + k;
        if (n >= N) break;
        float scl = 0.5f * (sc0[k] * i2c + g_skip_s[n * 64 + lane]);
        float sch = 0.5f * (sc1[k] * i2c + g_skip_s[n * 64 + 32 + lane]);
        float feat = silu_f(scl);
        float gate = silu_f(sch);

        float vg0 = 0.5f * (vc0[k] * i2c + g_skip_v[n * 96 +      lane]) * gate;
        float vg1 = 0.5f * (vc1[k] * i2c + g_skip_v[n * 96 + 32 + lane]) * gate;
        float vg2 = 0.5f * (vc2[k] * i2c + g_skip_v[n * 96 + 64 + lane]) * gate;

        float* o = out + (size_t)n * 128;
        o[lane] = feat;
        o[32 + 3 * lane + 0] = vg0;
        o[32 + 3 * lane + 1] = vg1;
        o[32 + 3 * lane + 2] = vg2;
    }
}

// ---------------------------------------------------------------------------
extern "C" void kernel_launch(void* const* d_in, const int* in_sizes, int n_in,
                              void* d_out, int out_size)
{
    const float* nf      = (const float*)d_in[0];
    const float* ef      = (const float*)d_in[1];
    const float* radial  = (const float*)d_in[2];
    const int*   snd     = (const int*)  d_in[3];
    const int*   rcv     = (const int*)  d_in[4];
    const int*   species = (const int*)  d_in[5];
    const float* Wus     = (const float*)d_in[6];
    const float* Wuv     = (const float*)d_in[7];
    const float* Wr1     = (const float*)d_in[8];
    const float* Wr2     = (const float*)d_in[9];
    const float* Wds     = (const float*)d_in[10];
    const float* Wdv     = (const float*)d_in[11];
    const float* Wss     = (const float*)d_in[12];
    const float* Wsv     = (const float*)d_in[13];
    float* out = (float*)d_out;

    int N = in_sizes[0] / 128;
    int E = in_sizes[3];

    int ewarps  = (E + 7) / 8;
    int eblocks = (ewarps + 7) / 8;
    int dwarps  = (N + 3) / 4;
    int dblocks = (dwarps + 7) / 8;

    node_up_kernel  <<<(N + 7) / 8, 256>>>(nf, species, Wus, Wuv, Wss, Wsv, N);
    edge_kernel     <<<eblocks, 256>>>(ef, radial, snd, rcv, Wr1, Wr2, E);
    node_down_kernel<<<dblocks, 256>>>(Wds, Wdv, out, N);
}

// round 17
// speedup vs baseline: 1.1668x; 1.0195x over previous
#include <cuda_runtime.h>

// Problem constants (fixed by the dataset)
#define MAXN 50000
#define MAXE 800000

typedef unsigned long long u64;

// Persistent device scratch (allocation-free rule: __device__ globals)
static __device__ __align__(16) float g_sup[MAXN * 32];     // s_up   [n][c]
static __device__ __align__(16) float g_vup[MAXN * 96];     // v_up   [n][x][c]
static __device__ __align__(16) float g_skip_s[MAXN * 64];  // skip_s [n][d]
static __device__ __align__(16) float g_skip_v[MAXN * 96];  // skip_v [n][x][c]
static __device__ __align__(16) float g_agg[MAXN * 256];    // [n][slot][c]

__device__ __forceinline__ float silu_f(float x) {
    return x / (1.0f + __expf(-x));
}

__device__ __forceinline__ void red_add_v4(float* p, float a, float b, float c, float d) {
    asm volatile("red.global.add.v4.f32 [%0], {%1,%2,%3,%4};"
                 :: "l"(p), "f"(a), "f"(b), "f"(c), "f"(d)
                 : "memory");
}

// ---- packed f32x2 helpers (Blackwell FFMA2 path) ----
__device__ __forceinline__ u64 pack2(float lo, float hi) {
    u64 r; asm("mov.b64 %0, {%1, %2};" : "=l"(r) : "f"(lo), "f"(hi)); return r;
}
__device__ __forceinline__ void unpack2(u64 p, float& lo, float& hi) {
    asm("mov.b64 {%0, %1}, %2;" : "=f"(lo), "=f"(hi) : "l"(p));
}
__device__ __forceinline__ u64 fma2(u64 a, u64 b, u64 c) {
    u64 d; asm("fma.rn.f32x2 %0, %1, %2, %3;" : "=l"(d) : "l"(a), "l"(b), "l"(c)); return d;
}
__device__ __forceinline__ u64 mul2(u64 a, u64 b) {
    u64 d; asm("mul.rn.f32x2 %0, %1, %2;" : "=l"(d) : "l"(a), "l"(b)); return d;
}

// ---------------------------------------------------------------------------
// Kernel A: per-node up-projection + species skip.
// Round-17 SINGLE CHANGE: s/v broadcasts via uniform LDS.128 from a per-warp
// smem float4 stage (same transformation that won in node_down round 16):
// 128 SHFL/warp -> 32 uniform LDS.128 + 4 STS wavefronts.
// Also zeroes this node's agg slab.
// ---------------------------------------------------------------------------
__global__ void node_up_kernel(const float* __restrict__ nf,
                               const int*   __restrict__ species,
                               const float* __restrict__ Wus,   // (32,32)
                               const float* __restrict__ Wuv,   // (32,32)
                               const float* __restrict__ Wss,   // (5,32,64)
                               const float* __restrict__ Wsv,   // (5,32,32)
                               int N)
{
    __shared__ __align__(16) float4 sm[8][32];   // [warp][c] = {s, v0, v1, v2}

    int warp = (blockIdx.x * blockDim.x + threadIdx.x) >> 5;
    int wib  = (threadIdx.x >> 5) & 7;
    int lane = threadIdx.x & 31;
    if (warp >= N) return;
    int n = warp;

    const float* nfp = nf + (size_t)n * 128;
    float s  = nfp[lane];
    float v0 = nfp[32 + lane * 3 + 0];
    float v1 = nfp[32 + lane * 3 + 1];
    float v2 = nfp[32 + lane * 3 + 2];
    int sp = species[n];
    const float* wss = Wss + sp * 2048;
    const float* wsv = Wsv + sp * 1024;

    sm[wib][lane] = make_float4(s, v0, v1, v2);
    __syncwarp();

    float sup = 0.f, vu0 = 0.f, vu1 = 0.f, vu2 = 0.f;
    float ss0 = 0.f, ss1 = 0.f, sv0 = 0.f, sv1 = 0.f, sv2 = 0.f;

    #pragma unroll
    for (int c = 0; c < 32; ++c) {
        float4 b = sm[wib][c];        // uniform LDS.128 broadcast
        float sb = b.x, b0 = b.y, b1 = b.z, b2 = b.w;
        sup = fmaf(sb, __ldg(Wus + c * 32 + lane), sup);
        float wu = __ldg(Wuv + c * 32 + lane);
        vu0 = fmaf(b0, wu, vu0);
        vu1 = fmaf(b1, wu, vu1);
        vu2 = fmaf(b2, wu, vu2);
        ss0 = fmaf(sb, __ldg(wss + c * 64 + lane), ss0);
        ss1 = fmaf(sb, __ldg(wss + c * 64 + 32 + lane), ss1);
        float wv = __ldg(wsv + c * 32 + lane);
        sv0 = fmaf(b0, wv, sv0);
        sv1 = fmaf(b1, wv, sv1);
        sv2 = fmaf(b2, wv, sv2);
    }

    const float isc = 0.17677669529663687f; // 1/sqrt(32)
    g_sup[n * 32 + lane]             = sup * isc;
    g_vup[n * 96 + 0 * 32 + lane]    = vu0 * isc;
    g_vup[n * 96 + 1 * 32 + lane]    = vu1 * isc;
    g_vup[n * 96 + 2 * 32 + lane]    = vu2 * isc;
    g_skip_s[n * 64 + lane]          = ss0 * isc;
    g_skip_s[n * 64 + 32 + lane]     = ss1 * isc;
    g_skip_v[n * 96 + 0 * 32 + lane] = sv0 * isc;
    g_skip_v[n * 96 + 1 * 32 + lane] = sv1 * isc;
    g_skip_v[n * 96 + 2 * 32 + lane] = sv2 * isc;

    #pragma unroll
    for (int k = 0; k < 2; ++k)
        *(float4*)(g_agg + n * 256 + (k * 32 + lane) * 4) = make_float4(0.f, 0.f, 0.f, 0.f);
}

// ---------------------------------------------------------------------------
// Kernel B: edge kernel (EXACT champion, UNCHANGED).
// ---------------------------------------------------------------------------
__global__ void __launch_bounds__(256, 3) edge_kernel(
    const float* __restrict__ ef,
    const float* __restrict__ radial,
    const int*   __restrict__ snd_,
    const int*   __restrict__ rcv_,
    const float* __restrict__ Wr1,   // (8,8)
    const float* __restrict__ Wr2,   // (8,128)
    int E)
{
    int warp = (blockIdx.x * blockDim.x + threadIdx.x) >> 5;
    int lane = threadIdx.x & 31;
    int base = warp * 8;
    if (base >= E) return;

    const float inv_sqrt8 = 0.35355339059327373f;
    const float inv_sqrt3 = 0.5773502691896258f;
    const float wk        = 0.08838834764831845f; // inv_sqrt8 * 1/sqrt(16)

    int grp  = lane >> 3;
    int pA   = (grp == 0) ? 0 : ((grp == 1) ? 3 : ((grp == 2) ? 1 : 2));
    int srcB = (grp < 2) ? lane + 16 : lane;
    int cidx = (lane & 7) * 4;
    int jj   = lane & 7;
    int loff = (lane >> 4) * 64 + (lane & 15) * 4;

    bool g1 = (grp == 1), g2 = (grp == 2), g3 = (grp == 3);
    bool g0 = (grp == 0);
    bool scalA = ((grp & 1) == 0);

    float wr1r[8];
    #pragma unroll
    for (int i = 0; i < 8; ++i) wr1r[i] = __ldg(Wr1 + i * 8 + jj);

    int wcol = pA * 32 + cidx;
    u64 wr2p0[8], wr2p1[8];
    #pragma unroll
    for (int q = 0; q < 8; ++q) {
        float4 wr = __ldg((const float4*)(Wr2 + q * 128 + wcol));
        wr2p0[q] = pack2(wr.x, wr.y);
        wr2p1[q] = pack2(wr.z, wr.w);
    }
    u64 wk2   = pack2(wk, wk);
    u64 zero2 = pack2(0.f, 0.f);

    int eic = base + jj; if (eic > E - 1) eic = E - 1;
    int snd8 = __ldg(snd_ + eic);
    int rcv8 = __ldg(rcv_ + eic);

    size_t rbase = (size_t)base * 4 + lane;
    size_t rmax  = (size_t)E * 4 - 1;
    if (rbase > rmax) rbase = rmax;
    float2 rv = __ldg((const float2*)radial + rbase);
    float rvx = rv.x, rvy = rv.y;

    float h0, h1;
    {
        int eb = (lane >> 3) * 4;
        float t0 = 0.f, t1 = 0.f;
        #pragma unroll
        for (int i = 0; i < 8; ++i) {
            int sl = eb + (i >> 1);
            float r0 = (i & 1) ? __shfl_sync(0xffffffffu, rvy, sl)
                               : __shfl_sync(0xffffffffu, rvx, sl);
            float r1 = (i & 1) ? __shfl_sync(0xffffffffu, rvy, sl + 16)
                               : __shfl_sync(0xffffffffu, rvx, sl + 16);
            t0 = fmaf(r0, wr1r[i], t0);
            t1 = fmaf(r1, wr1r[i], t1);
        }
        h0 = silu_f(t0 * inv_sqrt8);
        h1 = silu_f(t1 * inv_sqrt8);
    }

    #pragma unroll
    for (int j = 0; j < 8; ++j) {
        bool vj = (base + j) < E;
        int snd = __shfl_sync(0xffffffffu, snd8, j);
        int rcv = __shfl_sync(0xffffffffu, rcv8, j);

        u64 w01 = zero2, w23 = zero2;
        #pragma unroll
        for (int q = 0; q < 8; ++q) {
            float hq = (j < 4) ? __shfl_sync(0xffffffffu, h0, (j & 3) * 8 + q)
                               : __shfl_sync(0xffffffffu, h1, (j & 3) * 8 + q);
            u64 h2 = pack2(hq, hq);
            w01 = fma2(h2, wr2p0[q], w01);
            w23 = fma2(h2, wr2p1[q], w23);
        }
        w01 = mul2(w01, wk2);
        w23 = mul2(w23, wk2);
        float wA0, wA1, wA2, wA3;
        unpack2(w01, wA0, wA1);
        unpack2(w23, wA2, wA3);

        float wB0 = __shfl_sync(0xffffffffu, wA0, srcB);
        float wB1 = __shfl_sync(0xffffffffu, wA1, srcB);
        float wB2 = __shfl_sync(0xffffffffu, wA2, srcB);
        float wB3 = __shfl_sync(0xffffffffu, wA3, srcB);

        int ee = vj ? (base + j) : (E - 1);
        float4 sh = __ldg((const float4*)ef + ee);           // broadcast

        const float* sup_row = g_sup + (size_t)snd * 32 + cidx;
        const float* vup_row = g_vup + (size_t)snd * 96 + cidx;
        float4 q1 = __ldg((const float4*)(scalA ? sup_row : vup_row));        // se | ve0
        float4 q2 = __ldg((const float4*)(g3 ? vup_row + 64 : vup_row + 32)); // ve1 | ve2
        float4 q3 = __ldg((const float4*)(vup_row + 64));                     // ve2

        float d0 = fmaf(q3.x, sh.w, fmaf(q2.x, sh.z, q1.x * sh.y));
        float d1 = fmaf(q3.y, sh.w, fmaf(q2.y, sh.z, q1.y * sh.y));
        float d2 = fmaf(q3.z, sh.w, fmaf(q2.z, sh.z, q1.z * sh.y));
        float d3 = fmaf(q3.w, sh.w, fmaf(q2.w, sh.z, q1.w * sh.y));

        float sA = g1 ? inv_sqrt3 : (g2 ? sh.y : sh.x);
        float sB = g0 ? sh.z : (g2 ? sh.w : sh.x);

        float bA0 = g1 ? d0 : q1.x;
        float bA1 = g1 ? d1 : q1.y;
        float bA2 = g1 ? d2 : q1.z;
        float bA3 = g1 ? d3 : q1.w;

        float bB0 = scalA ? q1.x : q2.x;
        float bB1 = scalA ? q1.y : q2.y;
        float bB2 = scalA ? q1.z : q2.z;
        float bB3 = scalA ? q1.w : q2.w;

        float* dst = g_agg + (size_t)rcv * 256 + loff;
        if (vj) {
            red_add_v4(dst,
                       (wA0 * sA) * bA0, (wA1 * sA) * bA1,
                       (wA2 * sA) * bA2, (wA3 * sA) * bA3);
            red_add_v4(dst + 128,
                       (wB0 * sB) * bB0, (wB1 * sB) * bB1,
                       (wB2 * sB) * bB2, (wB3 * sB) * bB3);
        }
    }
}

// ---------------------------------------------------------------------------
// Kernel C: down-projection + skip + gated output, 4 nodes/warp,
// smem-staged uniform-LDS broadcasts (EXACT round-16 champion, UNCHANGED).
// ---------------------------------------------------------------------------
__global__ void __launch_bounds__(256) node_down_kernel(
    const float* __restrict__ Wds,  // (64,64)
    const float* __restrict__ Wdv,  // (64,32)
    float* __restrict__ out,
    int N)
{
    __shared__ __align__(16) float sm[8][1024];   // [warp][node*256 + slot*32 + c]

    int warp = (blockIdx.x * blockDim.x + threadIdx.x) >> 5;
    int wib  = (threadIdx.x >> 5) & 7;
    int lane = threadIdx.x & 31;
    int n0 = warp * 4;
    if (n0 >= N) return;

    #pragma unroll
    for (int k = 0; k < 4; ++k) {
        int n = n0 + k; if (n > N - 1) n = N - 1;
        const float4* src = (const float4*)(g_agg + (size_t)n * 256);
        float4 x0 = __ldg(src + lane);
        float4 x1 = __ldg(src + 32 + lane);
        *(float4*)&sm[wib][k * 256 + lane * 4]       = x0;
        *(float4*)&sm[wib][k * 256 + 128 + lane * 4] = x1;
    }
    __syncwarp();

    float sc0[4] = {0.f, 0.f, 0.f, 0.f}, sc1[4] = {0.f, 0.f, 0.f, 0.f};
    float vc0[4] = {0.f, 0.f, 0.f, 0.f}, vc1[4] = {0.f, 0.f, 0.f, 0.f};
    float vc2[4] = {0.f, 0.f, 0.f, 0.f};

    for (int cg = 0; cg < 8; ++cg) {
        float wsa[4], wsb[4], wsa2[4], wsb2[4], wv0[4], wv1[4];
        #pragma unroll
        for (int i = 0; i < 4; ++i) {
            int c = cg * 4 + i;
            wsa[i]  = __ldg(Wds + c * 64 + lane);
            wsb[i]  = __ldg(Wds + (32 + c) * 64 + lane);
            wsa2[i] = __ldg(Wds + c * 64 + 32 + lane);
            wsb2[i] = __ldg(Wds + (32 + c) * 64 + 32 + lane);
            wv0[i]  = __ldg(Wdv + c * 32 + lane);
            wv1[i]  = __ldg(Wdv + (32 + c) * 32 + lane);
        }
        #pragma unroll
        for (int k = 0; k < 4; ++k) {
            const float* a = &sm[wib][k * 256 + cg * 4];
            {
                float4 L = *(const float4*)(a);
                float4 H = *(const float4*)(a + 32);
                sc0[k] = fmaf(L.x, wsa[0],  sc0[k]);
                sc0[k] = fmaf(L.y, wsa[1],  sc0[k]);
                sc0[k] = fmaf(L.z, wsa[2],  sc0[k]);
                sc0[k] = fmaf(L.w, wsa[3],  sc0[k]);
                sc0[k] = fmaf(H.x, wsb[0],  sc0[k]);
                sc0[k] = fmaf(H.y, wsb[1],  sc0[k]);
                sc0[k] = fmaf(H.z, wsb[2],  sc0[k]);
                sc0[k] = fmaf(H.w, wsb[3],  sc0[k]);
                sc1[k] = fmaf(L.x, wsa2[0], sc1[k]);
                sc1[k] = fmaf(L.y, wsa2[1], sc1[k]);
                sc1[k] = fmaf(L.z, wsa2[2], sc1[k]);
                sc1[k] = fmaf(L.w, wsa2[3], sc1[k]);
                sc1[k] = fmaf(H.x, wsb2[0], sc1[k]);
                sc1[k] = fmaf(H.y, wsb2[1], sc1[k]);
                sc1[k] = fmaf(H.z, wsb2[2], sc1[k]);
                sc1[k] = fmaf(H.w, wsb2[3], sc1[k]);
            }
            {
                float4 L = *(const float4*)(a + 64);
                float4 H = *(const float4*)(a + 96);
                vc0[k] = fmaf(L.x, wv0[0], vc0[k]);
                vc0[k] = fmaf(L.y, wv0[1], vc0[k]);
                vc0[k] = fmaf(L.z, wv0[2], vc0[k]);
                vc0[k] = fmaf(L.w, wv0[3], vc0[k]);
                vc0[k] = fmaf(H.x, wv1[0], vc0[k]);
                vc0[k] = fmaf(H.y, wv1[1], vc0[k]);
                vc0[k] = fmaf(H.z, wv1[2], vc0[k]);
                vc0[k] = fmaf(H.w, wv1[3], vc0[k]);
            }
            {
                float4 L = *(const float4*)(a + 128);
                float4 H = *(const float4*)(a + 160);
                vc1[k] = fmaf(L.x, wv0[0], vc1[k]);
                vc1[k] = fmaf(L.y, wv0[1], vc1[k]);
                vc1[k] = fmaf(L.z, wv0[2], vc1[k]);
                vc1[k] = fmaf(L.w, wv0[3], vc1[k]);
                vc1[k] = fmaf(H.x, wv1[0], vc1[k]);
                vc1[k] = fmaf(H.y, wv1[1], vc1[k]);
                vc1[k] = fmaf(H.z, wv1[2], vc1[k]);
                vc1[k] = fmaf(H.w, wv1[3], vc1[k]);
            }
            {
                float4 L = *(const float4*)(a + 192);
                float4 H = *(const float4*)(a + 224);
                vc2[k] = fmaf(L.x, wv0[0], vc2[k]);
                vc2[k] = fmaf(L.y, wv0[1], vc2[k]);
                vc2[k] = fmaf(L.z, wv0[2], vc2[k]);
                vc2[k] = fmaf(L.w, wv0[3], vc2[k]);
                vc2[k] = fmaf(H.x, wv1[0], vc2[k]);
                vc2[k] = fmaf(H.y, wv1[1], vc2[k]);
                vc2[k] = fmaf(H.z, wv1[2], vc2[k]);
                vc2[k] = fmaf(H.w, wv1[3], vc2[k]);
            }
        }
    }

    const float i2c = 0.125f; // 1/sqrt(64)
    #pragma unroll
    for (int k = 0; k < 4; ++k) {
        int n = n0 + k;
        if (n >= N) break;
        float scl = 0.5f * (sc0[k] * i2c + g_skip_s[n * 64 + lane]);
        float sch = 0.5f * (sc1[k] * i2c + g_skip_s[n * 64 + 32 + lane]);
        float feat = silu_f(scl);
        float gate = silu_f(sch);

        float vg0 = 0.5f * (vc0[k] * i2c + g_skip_v[n * 96 +      lane]) * gate;
        float vg1 = 0.5f * (vc1[k] * i2c + g_skip_v[n * 96 + 32 + lane]) * gate;
        float vg2 = 0.5f * (vc2[k] * i2c + g_skip_v[n * 96 + 64 + lane]) * gate;

        float* o = out + (size_t)n * 128;
        o[lane] = feat;
        o[32 + 3 * lane + 0] = vg0;
        o[32 + 3 * lane + 1] = vg1;
        o[32 + 3 * lane + 2] = vg2;
    }
}

// ---------------------------------------------------------------------------
extern "C" void kernel_launch(void* const* d_in, const int* in_sizes, int n_in,
                              void* d_out, int out_size)
{
    const float* nf      = (const float*)d_in[0];
    const float* ef      = (const float*)d_in[1];
    const float* radial  = (const float*)d_in[2];
    const int*   snd     = (const int*)  d_in[3];
    const int*   rcv     = (const int*)  d_in[4];
    const int*   species = (const int*)  d_in[5];
    const float* Wus     = (const float*)d_in[6];
    const float* Wuv     = (const float*)d_in[7];
    const float* Wr1     = (const float*)d_in[8];
    const float* Wr2     = (const float*)d_in[9];
    const float* Wds     = (const float*)d_in[10];
    const float* Wdv     = (const float*)d_in[11];
    const float* Wss     = (const float*)d_in[12];
    const float* Wsv     = (const float*)d_in[13];
    float* out = (float*)d_out;

    int N = in_sizes[0] / 128;
    int E = in_sizes[3];

    int ewarps  = (E + 7) / 8;
    int eblocks = (ewarps + 7) / 8;
    int dwarps  = (N + 3) / 4;
    int dblocks = (dwarps + 7) / 8;

    node_up_kernel  <<<(N + 7) / 8, 256>>>(nf, species, Wus, Wuv, Wss, Wsv, N);
    edge_kernel     <<<eblocks, 256>>>(ef, radial, snd, rcv, Wr1, Wr2, E);
    node_down_kernel<<<dblocks, 256>>>(Wds, Wdv, out, N);
}